// round 12
// baseline (speedup 1.0000x reference)
#include <cuda_runtime.h>

#define NEGF  (-1e30f)
#define LOG2E (1.4426950408889634f)
#define LN2   (0.6931471805599453f)
#define MAXB  4096
#define NW    11
#define NT    (NW * 32)          // 352 threads
#define PMAX  272
#define EBIAS 100                // per-superstep renorm target: warp max = 2^EBIAS

__device__ float g_loss[MAXB];

__device__ __forceinline__ float ex2f_(float x){ float y; asm("ex2.approx.f32 %0,%1;":"=f"(y):"f"(x)); return y; }
__device__ __forceinline__ float lg2f_(float x){ float y; asm("lg2.approx.f32 %0,%1;":"=f"(y):"f"(x)); return y; }

__device__ __forceinline__ float lae2(float x, float y) {
    float m = fmaxf(x, y);
    float d = -fabsf(x - y);
    return m + lg2f_(1.0f + ex2f_(d));
}

// v * 2^d, exact power-of-2 factors, d clamped to [-252, 252]
__device__ __forceinline__ float ldx2(float v, int d) {
    d = d > 252 ? 252 : (d < -252 ? -252 : d);
    int d1 = d >> 1, d2 = d - d1;
    v *= __int_as_float((127 + d1) << 23);
    v *= __int_as_float((127 + d2) << 23);
    return v;
}

__device__ __forceinline__ void cp4(float* s, const float* g) {
    unsigned sa = (unsigned)__cvta_generic_to_shared(s);
    asm volatile("cp.async.ca.shared.global [%0], [%1], 4;" :: "r"(sa), "l"(g));
}
__device__ __forceinline__ void cp_commit() { asm volatile("cp.async.commit_group;"); }
__device__ __forceinline__ void cp_wait1()  { asm volatile("cp.async.wait_group 1;"); }

// Pair p = (2p blank, 2p+1 label tg[p]).  p = 24*warp + lane.
// Warps >=1: lanes 0-7 left halo (redundant), lanes 8-31 owned.
// Alphas LINEAR at per-warp scale E; superstep-start joint renorm in the
// exponent domain (overflow-free).  ex2 conversions and cp.async refills are
// software-pipelined through the 8-step shfl chain to avoid pipe bursts.
__global__ void __launch_bounds__(NT) ctc_fwd_kernel(
    const float* __restrict__ log_probs,   // [B, T, V]
    const int*   __restrict__ in_len,
    const int*   __restrict__ targets,     // [B, S]
    const int*   __restrict__ tgt_len,
    int T, int V, int S)
{
    __shared__ float sa0[2 * PMAX];
    __shared__ float sa1[2 * PMAX];
    __shared__ float stgl[16 * NT];        // [2][8][NT] thread-private slots
    __shared__ float stgb[16 * NW];        // [2][8][NW] warp-private blank slots
    __shared__ int   sE[2 * NW];           // per-warp scale, double buffered
    __shared__ int   sEf[NW];              // final scales

    const int b    = blockIdx.x;
    const int j    = threadIdx.x;
    const int warp = j >> 5;
    const int lane = j & 31;
    const int p    = 24 * warp + lane;
    const bool owned = (warp == 0) || (lane >= 8);

    int L = tgt_len[b]; if (L > S) L = S;
    int Tin = in_len[b];
    if (Tin > T) Tin = T;
    if (Tin < 1) Tin = 1;

    const float* lp = log_probs + (size_t)b * T * V;
    const int*   tg = targets   + (size_t)b * S;

    const bool act  = (p <= L);
    const bool act1 = (p <  L);
    const bool wact = (24 * warp) <= L;
    int   lab = 0;
    float skf = 0.0f;
    if (act1) {
        lab = tg[p];
        skf = (p >= 1 && lab != tg[p - 1]) ? 1.0f : 0.0f;
    }

    // t = 0: linear alphas at scale E = -EBIAS (max ~= 2^EBIAS)
    float la0 = 0.0f, la1 = 0.0f;
    int   E   = -EBIAS;
    if (p == 0) {
        la0 = ex2f_(lp[0] * LOG2E + (float)EBIAS);
        if (L > 0) la1 = ex2f_(lp[lab] * LOG2E + (float)EBIAS);
    }
    if (owned) { sa0[p] = la0; sa1[p] = la1; }
    if (lane == 0) sE[warp] = E;

    // prologue: stage t=1..8 -> buf0, t=9..16 -> buf1
    if (act) {
        #pragma unroll
        for (int k = 0; k < 8; ++k) { int t = 1 + k; if (t < Tin) cp4(&stgl[k * NT + j], lp + (size_t)t * V + lab); }
    }
    if (wact && lane >= 24) { int k = lane - 24, t = 1 + k; if (t < Tin) cp4(&stgb[k * NW + warp], lp + (size_t)t * V); }
    cp_commit();
    if (act) {
        #pragma unroll
        for (int k = 0; k < 8; ++k) { int t = 9 + k; if (t < Tin) cp4(&stgl[(8 + k) * NT + j], lp + (size_t)t * V + lab); }
    }
    if (wact && lane >= 24) { int k = lane - 24, t = 9 + k; if (t < Tin) cp4(&stgb[(8 + k) * NW + warp], lp + (size_t)t * V); }
    cp_commit();

    int cur = 0;
    for (int tb = 1; tb < Tin; tb += 8, cur ^= 1) {
        cp_wait1();
        __syncthreads();                   // stage[cur] + sa[cur] + sE[cur] visible

        if (wact) {
            // halo refresh: candidate values at scale Eh
            const int En = (warp > 0) ? sE[cur * NW + (warp - 1)] : E;
            float h0 = la0, h1 = la1;
            int   Eh = E;
            if (!owned) {
                h0 = sa0[cur * PMAX + p];
                h1 = sa1[cur * PMAX + p];
                Eh = En;
            }

            // joint renorm in exponent domain: warp max -> exactly 2^EBIAS
            int ie = -0x40000000;
            if (h0 > 0.0f) { int e0 = ((__float_as_int(h0) >> 23) & 255) + Eh; ie = ie > e0 ? ie : e0; }
            if (h1 > 0.0f) { int e1 = ((__float_as_int(h1) >> 23) & 255) + Eh; ie = ie > e1 ? ie : e1; }
            ie = __reduce_max_sync(0xffffffffu, ie);
            if (ie > -0x20000000) {        // some mass in warp
                const int Enew = (ie - 127) - EBIAS;
                la0 = ldx2(h0, Eh - Enew); // shift bounded: no overflow possible
                la1 = ldx2(h1, Eh - Enew);
                E = Enew;
            }

            const int rem = (Tin - tb) < 8 ? (Tin - tb) : 8;   // block-uniform

            // pre-convert slots 0..2 (pl forced to 0 for inactive threads:
            // dead positions then stay exactly 0 through the recursion)
            float pl[8], pb[8];
            #pragma unroll
            for (int k = 0; k < 3; ++k) {
                pb[k] = ex2f_(stgb[(cur * 8 + k) * NW + warp] * LOG2E);
                float c = ex2f_(stgl[(cur * 8 + k) * NT + j] * LOG2E);
                pl[k] = act1 ? c : 0.0f;
            }

            // ---- 8 steps: shfl+FMA chain with pipelined ex2 + cp.async ----
            #pragma unroll
            for (int k = 0; k < 8; ++k) {
                if (k >= rem) break;       // uniform time-tail freeze
                if (k + 3 < 8) {           // convert slot k+3 (hidden in stalls)
                    pb[k + 3] = ex2f_(stgb[(cur * 8 + k + 3) * NW + warp] * LOG2E);
                    float c = ex2f_(stgl[(cur * 8 + k + 3) * NT + j] * LOG2E);
                    pl[k + 3] = act1 ? c : 0.0f;
                }
                {                          // refill slot k for t = tb+16+k
                    int tn = tb + 16 + k;
                    if (act && tn < Tin) cp4(&stgl[(cur * 8 + k) * NT + j], lp + (size_t)tn * V + lab);
                }
                if (k == 0 && lane >= 24) {
                    int kk = lane - 24, tn = tb + 16 + kk;
                    if (tn < Tin) cp4(&stgb[(cur * 8 + kk) * NW + warp], lp + (size_t)tn * V);
                }
                float o = __shfl_up_sync(0xffffffffu, la1, 1);
                o = (lane == 0) ? 0.0f : o;
                float n1 = fmaf(skf, o, la1 + la0) * pl[k];
                float n0 = (la0 + o) * pb[k];
                la0 = n0;
                la1 = n1;
            }
        }
        cp_commit();                       // uniform; closes this superstep's refills

        const int nxt = cur ^ 1;
        if (owned) { sa0[nxt * PMAX + p] = la0; sa1[nxt * PMAX + p] = la1; }
        if (lane == 0) sE[nxt * NW + warp] = E;
    }

    // epilogue
    __syncthreads();
    if (owned) { sa0[p] = la0; sa1[p] = la1; }
    if (lane == 0) sEf[warp] = E;
    __syncthreads();
    if (j == 0) {
        // owner warp of pair q: warp 0 owns 0..31; warp w>=1 owns 24w+8..24w+31
        int wx = (L <= 31) ? 0 : (L - 8) / 24;
        float v0 = sa0[L];
        float x = (v0 > 0.0f) ? (lg2f_(v0) + (float)sEf[wx]) : NEGF;
        float y = NEGF;
        if (L > 0) {
            int q = L - 1;
            int wy = (q <= 31) ? 0 : (q - 8) / 24;
            float v1 = sa1[q];
            if (v1 > 0.0f) y = lg2f_(v1) + (float)sEf[wy];
        }
        float ll2 = lae2(x, y);
        float loss = -ll2 * LN2;
        if (!(loss <= 1e29f)) loss = 0.0f;         // zero_infinity (+ nan/inf guard)
        int Lm = (L > 0) ? L : 1;
        g_loss[b] = loss / (float)Lm;
    }
}

__global__ void ctc_reduce_kernel(float* __restrict__ out, int B) {
    int lane = threadIdx.x;
    float s = 0.0f;
    for (int i = lane; i < B; i += 32) s += g_loss[i];
    #pragma unroll
    for (int off = 16; off; off >>= 1)
        s += __shfl_xor_sync(0xffffffffu, s, off);
    if (lane == 0) out[0] = s / (float)B;
}

extern "C" void kernel_launch(void* const* d_in, const int* in_sizes, int n_in,
                              void* d_out, int out_size) {
    const float* log_probs = (const float*)d_in[0];
    const int*   in_len    = (const int*)d_in[1];
    const int*   targets   = (const int*)d_in[2];
    const int*   tgt_len   = (const int*)d_in[3];

    const int B = in_sizes[1];
    const int S = in_sizes[2] / B;
    const int V = 128;
    const int T = in_sizes[0] / (B * V);

    ctc_fwd_kernel<<<B, NT>>>(log_probs, in_len, targets, tgt_len, T, V, S);
    ctc_reduce_kernel<<<1, 32>>>((float*)d_out, B);
}

// round 13
// speedup vs baseline: 1.2087x; 1.2087x over previous
#include <cuda_runtime.h>

#define NEGF  (-1e30f)
#define LOG2E (1.4426950408889634f)
#define LN2   (0.6931471805599453f)
#define MAXB  4096
#define NW    11
#define NT    (NW * 32)          // 352 threads
#define PMAX  272
#define EBIAS 100                // per-superstep renorm target: warp max = 2^EBIAS

__device__ float g_loss[MAXB];
__device__ unsigned int g_ticket = 0;

__device__ __forceinline__ float ex2f_(float x){ float y; asm("ex2.approx.f32 %0,%1;":"=f"(y):"f"(x)); return y; }
__device__ __forceinline__ float lg2f_(float x){ float y; asm("lg2.approx.f32 %0,%1;":"=f"(y):"f"(x)); return y; }

__device__ __forceinline__ float lae2(float x, float y) {
    float m = fmaxf(x, y);
    float d = -fabsf(x - y);
    return m + lg2f_(1.0f + ex2f_(d));
}

// v * 2^d, exact power-of-2 factors, d clamped to [-252, 252]
__device__ __forceinline__ float ldx2(float v, int d) {
    d = d > 252 ? 252 : (d < -252 ? -252 : d);
    int d1 = d >> 1, d2 = d - d1;
    v *= __int_as_float((127 + d1) << 23);
    v *= __int_as_float((127 + d2) << 23);
    return v;
}

__device__ __forceinline__ void cp4(float* s, const float* g) {
    unsigned sa = (unsigned)__cvta_generic_to_shared(s);
    asm volatile("cp.async.ca.shared.global [%0], [%1], 4;" :: "r"(sa), "l"(g));
}
__device__ __forceinline__ void cp_commit() { asm volatile("cp.async.commit_group;"); }
__device__ __forceinline__ void cp_wait1()  { asm volatile("cp.async.wait_group 1;"); }

// Pair p = (2p blank, 2p+1 label tg[p]).  p = 24*warp + lane.
// Warps >=1: lanes 0-7 left halo (redundant), lanes 8-31 owned.
// Alphas LINEAR at per-warp scale E (actual = la * 2^E); superstep-start joint
// renorm in the exponent domain (overflow-free, 249-bit tail window).
// Final deterministic batch reduction fused via last-block ticket.
__global__ void __launch_bounds__(NT) ctc_fwd_kernel(
    const float* __restrict__ log_probs,   // [B, T, V]
    const int*   __restrict__ in_len,
    const int*   __restrict__ targets,     // [B, S]
    const int*   __restrict__ tgt_len,
    float* __restrict__ out,
    int T, int V, int S, int B)
{
    __shared__ float sa0[2 * PMAX];
    __shared__ float sa1[2 * PMAX];
    __shared__ float stgl[16 * NT];        // [2][8][NT] thread-private slots
    __shared__ float stgb[16 * NW];        // [2][8][NW] warp-private blank slots
    __shared__ int   sE[2 * NW];           // per-warp scale, double buffered
    __shared__ int   sEf[NW];              // final scales
    __shared__ unsigned int s_rank;

    const int b    = blockIdx.x;
    const int j    = threadIdx.x;
    const int warp = j >> 5;
    const int lane = j & 31;
    const int p    = 24 * warp + lane;
    const bool owned = (warp == 0) || (lane >= 8);

    int L = tgt_len[b]; if (L > S) L = S;
    int Tin = in_len[b];
    if (Tin > T) Tin = T;
    if (Tin < 1) Tin = 1;

    const float* lp = log_probs + (size_t)b * T * V;
    const int*   tg = targets   + (size_t)b * S;

    const bool act  = (p <= L);
    const bool act1 = (p <  L);
    const bool wact = (24 * warp) <= L;
    int   lab = 0;
    float skf = 0.0f;
    if (act1) {
        lab = tg[p];
        skf = (p >= 1 && lab != tg[p - 1]) ? 1.0f : 0.0f;
    }

    // t = 0: linear alphas at scale E = -EBIAS (max ~= 2^EBIAS)
    float la0 = 0.0f, la1 = 0.0f;
    int   E   = -EBIAS;
    if (p == 0) {
        la0 = ex2f_(lp[0] * LOG2E + (float)EBIAS);
        if (L > 0) la1 = ex2f_(lp[lab] * LOG2E + (float)EBIAS);
    }
    if (owned) { sa0[p] = la0; sa1[p] = la1; }
    if (lane == 0) sE[warp] = E;

    // prologue: stage t=1..8 -> buf0, t=9..16 -> buf1
    if (act) {
        #pragma unroll
        for (int k = 0; k < 8; ++k) { int t = 1 + k; if (t < Tin) cp4(&stgl[k * NT + j], lp + (size_t)t * V + lab); }
    }
    if (wact && lane >= 24) { int k = lane - 24, t = 1 + k; if (t < Tin) cp4(&stgb[k * NW + warp], lp + (size_t)t * V); }
    cp_commit();
    if (act) {
        #pragma unroll
        for (int k = 0; k < 8; ++k) { int t = 9 + k; if (t < Tin) cp4(&stgl[(8 + k) * NT + j], lp + (size_t)t * V + lab); }
    }
    if (wact && lane >= 24) { int k = lane - 24, t = 9 + k; if (t < Tin) cp4(&stgb[(8 + k) * NW + warp], lp + (size_t)t * V); }
    cp_commit();

    int cur = 0;
    for (int tb = 1; tb < Tin; tb += 8, cur ^= 1) {
        cp_wait1();
        __syncthreads();                   // stage[cur] + sa[cur] + sE[cur] visible

        if (wact) {
            // halo refresh: candidate values at scale Eh
            const int En = (warp > 0) ? sE[cur * NW + (warp - 1)] : E;
            float h0 = la0, h1 = la1;
            int   Eh = E;
            if (!owned) {
                h0 = sa0[cur * PMAX + p];
                h1 = sa1[cur * PMAX + p];
                Eh = En;
            }

            // joint renorm in exponent domain: warp max -> exactly 2^EBIAS
            int ie = -0x40000000;
            if (h0 > 0.0f) { int e0 = ((__float_as_int(h0) >> 23) & 255) + Eh; ie = ie > e0 ? ie : e0; }
            if (h1 > 0.0f) { int e1 = ((__float_as_int(h1) >> 23) & 255) + Eh; ie = ie > e1 ? ie : e1; }
            ie = __reduce_max_sync(0xffffffffu, ie);
            if (ie > -0x20000000) {        // some mass in warp
                const int Enew = (ie - 127) - EBIAS;
                la0 = ldx2(h0, Eh - Enew); // shift bounded: no overflow possible
                la1 = ldx2(h1, Eh - Enew);
                E = Enew;
            }

            // staged log-probs -> linear registers (ALL before refills: no WAR)
            float pl[8], pb[8];
            #pragma unroll
            for (int k = 0; k < 8; ++k) {
                pb[k] = ex2f_(stgb[(cur * 8 + k) * NW + warp] * LOG2E);
                pl[k] = ex2f_(stgl[(cur * 8 + k) * NT + j]   * LOG2E);
            }

            // refill stage[cur] for t = tb+16..tb+23 (self-owned slots)
            if (act) {
                #pragma unroll
                for (int k = 0; k < 8; ++k) { int tn = tb + 16 + k; if (tn < Tin) cp4(&stgl[(cur * 8 + k) * NT + j], lp + (size_t)tn * V + lab); }
            }
            if (lane >= 24) { int k = lane - 24, tn = tb + 16 + k; if (tn < Tin) cp4(&stgb[(cur * 8 + k) * NW + warp], lp + (size_t)tn * V); }

            int rem = Tin - tb; if (rem > 8) rem = 8;
            const int rem0 = act  ? rem : 0;
            const int rem1 = act1 ? rem : 0;

            // ---- 8 steps: pure shfl + FMA, zero MUFU on the chain ----
            #pragma unroll
            for (int k = 0; k < 8; ++k) {
                float o = __shfl_up_sync(0xffffffffu, la1, 1);
                o = (lane == 0) ? 0.0f : o;
                float base = la1 + la0;
                float n1 = fmaf(skf, o, base) * pl[k];
                float n0 = (la0 + o) * pb[k];
                la0 = (k < rem0) ? n0 : la0;
                la1 = (k < rem1) ? n1 : la1;
            }
        }
        cp_commit();                       // uniform; pairs with refills above

        const int nxt = cur ^ 1;
        if (owned) { sa0[nxt * PMAX + p] = la0; sa1[nxt * PMAX + p] = la1; }
        if (lane == 0) sE[nxt * NW + warp] = E;
    }

    // epilogue: per-batch loss
    __syncthreads();
    if (owned) { sa0[p] = la0; sa1[p] = la1; }
    if (lane == 0) sEf[warp] = E;
    __syncthreads();
    if (j == 0) {
        // owner warp of pair q: warp 0 owns 0..31; warp w>=1 owns 24w+8..24w+31
        int wx = (L <= 31) ? 0 : (L - 8) / 24;
        float v0 = sa0[L];
        float x = (v0 > 0.0f) ? (lg2f_(v0) + (float)sEf[wx]) : NEGF;
        float y = NEGF;
        if (L > 0) {
            int q = L - 1;
            int wy = (q <= 31) ? 0 : (q - 8) / 24;
            float v1 = sa1[q];
            if (v1 > 0.0f) y = lg2f_(v1) + (float)sEf[wy];
        }
        float ll2 = lae2(x, y);
        float loss = -ll2 * LN2;
        if (!(loss <= 1e29f)) loss = 0.0f;         // zero_infinity (+ nan/inf guard)
        int Lm = (L > 0) ? L : 1;
        g_loss[b] = loss / (float)Lm;
    }

    // fused deterministic reduction: last block to arrive sums in fixed order
    __threadfence();
    __syncthreads();
    if (j == 0) s_rank = atomicAdd(&g_ticket, 1u);
    __syncthreads();
    if (s_rank == (unsigned)(gridDim.x - 1)) {
        if (warp == 0) {
            float s = 0.0f;
            for (int i = lane; i < B; i += 32) s += g_loss[i];
            #pragma unroll
            for (int off = 16; off; off >>= 1)
                s += __shfl_xor_sync(0xffffffffu, s, off);
            if (lane == 0) {
                out[0] = s / (float)B;
                g_ticket = 0;              // reset for next (graph-replayed) call
            }
        }
    }
}

extern "C" void kernel_launch(void* const* d_in, const int* in_sizes, int n_in,
                              void* d_out, int out_size) {
    const float* log_probs = (const float*)d_in[0];
    const int*   in_len    = (const int*)d_in[1];
    const int*   targets   = (const int*)d_in[2];
    const int*   tgt_len   = (const int*)d_in[3];

    const int B = in_sizes[1];
    const int S = in_sizes[2] / B;
    const int V = 128;
    const int T = in_sizes[0] / (B * V);

    ctc_fwd_kernel<<<B, NT>>>(log_probs, in_len, targets, tgt_len,
                              (float*)d_out, T, V, S, B);
}